// round 1
// baseline (speedup 1.0000x reference)
#include <cuda_runtime.h>
#include <math.h>

#define TT   2048
#define DD   1024
#define NH   16
#define HDIM 64
#define WIN  128
#define PSTR 132

// ---------------- scratch (static device globals; no allocation) ----------
__device__ float g_buf[TT * DD];
__device__ float v_buf[TT * DD];
__device__ float o_buf[TT * DD];
__device__ float norm_buf[NH * TT];
__device__ float denom_buf[NH * TT];
__device__ float suminv_buf[NH];
__device__ float p_buf[(size_t)NH * TT * PSTR];

// ---------------- SGEMM: C[MxN] = A[MxK] * B[NxK]^T + bias[N] -------------
#define BM 128
#define BN 128
#define BKK 16
#define TM 8
#define TN 8

__device__ __forceinline__ void sgemm_body(
    const float* __restrict__ A, const float* __restrict__ B,
    const float* __restrict__ bias, float* __restrict__ C,
    int K, int N, int bx, int by)
{
    __shared__ float As[BKK][BM];
    __shared__ float Bs[BKK][BN];

    const int tid = threadIdx.x;          // 256 threads
    const int tx  = tid & 15;
    const int ty  = tid >> 4;
    const int m0  = by * BM;
    const int n0  = bx * BN;

    float acc[TM][TN];
#pragma unroll
    for (int i = 0; i < TM; ++i)
#pragma unroll
        for (int j = 0; j < TN; ++j) acc[i][j] = 0.f;

#pragma unroll 1
    for (int k0 = 0; k0 < K; k0 += BKK) {
#pragma unroll
        for (int l = 0; l < 2; ++l) {
            int li  = tid + l * 256;
            int row = li >> 2;            // 0..127
            int kq  = li & 3;             // 0..3 (float4 along K)
            float4 va = *(const float4*)(A + (size_t)(m0 + row) * K + k0 + kq * 4);
            As[kq * 4 + 0][row] = va.x;
            As[kq * 4 + 1][row] = va.y;
            As[kq * 4 + 2][row] = va.z;
            As[kq * 4 + 3][row] = va.w;
            float4 vb = *(const float4*)(B + (size_t)(n0 + row) * K + k0 + kq * 4);
            Bs[kq * 4 + 0][row] = vb.x;
            Bs[kq * 4 + 1][row] = vb.y;
            Bs[kq * 4 + 2][row] = vb.z;
            Bs[kq * 4 + 3][row] = vb.w;
        }
        __syncthreads();

#pragma unroll
        for (int kk = 0; kk < BKK; ++kk) {
            float ar[TM], br[TN];
            *(float4*)&ar[0] = *(const float4*)&As[kk][ty * TM];
            *(float4*)&ar[4] = *(const float4*)&As[kk][ty * TM + 4];
            *(float4*)&br[0] = *(const float4*)&Bs[kk][tx * TN];
            *(float4*)&br[4] = *(const float4*)&Bs[kk][tx * TN + 4];
#pragma unroll
            for (int i = 0; i < TM; ++i)
#pragma unroll
                for (int j = 0; j < TN; ++j)
                    acc[i][j] = fmaf(ar[i], br[j], acc[i][j]);
        }
        __syncthreads();
    }

    float bb[TN];
#pragma unroll
    for (int j = 0; j < TN; ++j) bb[j] = bias[n0 + tx * TN + j];

#pragma unroll
    for (int i = 0; i < TM; ++i) {
        float* cp = C + (size_t)(m0 + ty * TM + i) * N + n0 + tx * TN;
        float4 o0 = make_float4(acc[i][0] + bb[0], acc[i][1] + bb[1],
                                acc[i][2] + bb[2], acc[i][3] + bb[3]);
        float4 o1 = make_float4(acc[i][4] + bb[4], acc[i][5] + bb[5],
                                acc[i][6] + bb[6], acc[i][7] + bb[7]);
        *(float4*)cp       = o0;
        *(float4*)(cp + 4) = o1;
    }
}

__global__ void __launch_bounds__(256)
k_gv(const float* __restrict__ x,
     const float* __restrict__ Wg, const float* __restrict__ bg,
     const float* __restrict__ Wv, const float* __restrict__ bv)
{
    const float* Bp; const float* bp; float* Cp;
    if (blockIdx.z == 0) { Bp = Wg; bp = bg; Cp = g_buf; }
    else                 { Bp = Wv; bp = bv; Cp = v_buf; }
    sgemm_body(x, Bp, bp, Cp, DD, DD, blockIdx.x, blockIdx.y);
}

__global__ void __launch_bounds__(256)
k_out(const float* __restrict__ Wo, const float* __restrict__ bo,
      float* __restrict__ out)
{
    sgemm_body(o_buf, Wo, bo, out, DD, DD, blockIdx.x, blockIdx.y);
}

// ---------------- per-(h,t) L2 norms of g ---------------------------------
__global__ void __launch_bounds__(256)
k_norm()
{
    const int r    = blockIdx.x * 8 + (threadIdx.x >> 5);  // r = h*TT + t
    const int lane = threadIdx.x & 31;
    const int h    = r >> 11;
    const int t    = r & (TT - 1);
    const float2 v = *(const float2*)(g_buf + (size_t)t * DD + h * HDIM + 2 * lane);
    float s = v.x * v.x + v.y * v.y;
#pragma unroll
    for (int o = 16; o > 0; o >>= 1) s += __shfl_xor_sync(0xffffffffu, s, o);
    if (lane == 0) norm_buf[r] = sqrtf(s);
}

// ---------------- windowed scores + gene_means denom ----------------------
__global__ void __launch_bounds__(128)
k_scores()
{
    const int i   = blockIdx.x;
    const int h   = blockIdx.y;
    const int tid = threadIdx.x;   // 128
    __shared__ float4 gi[16];
    __shared__ float  sred[4];

    if (tid < 16)
        gi[tid] = ((const float4*)(g_buf + (size_t)i * DD + h * HDIM))[tid];
    __syncthreads();

    const int    jstart = (i > WIN) ? (i - WIN) : 0;
    const int    cnt    = i - jstart + 1;          // <= 129
    const float  ni     = norm_buf[h * TT + i];
    const size_t row    = (size_t)(h * TT + i);

    float lsum = 0.f;
    for (int jj = tid; jj < cnt; jj += 128) {
        const int j = jstart + jj;
        const float4* gj = (const float4*)(g_buf + (size_t)j * DD + h * HDIM);
        float dot = 0.f;
#pragma unroll
        for (int q = 0; q < 16; ++q) {
            float4 a = gi[q];
            float4 b = gj[q];
            dot = fmaf(a.x, b.x, dot);
            dot = fmaf(a.y, b.y, dot);
            dot = fmaf(a.z, b.z, dot);
            dot = fmaf(a.w, b.w, dot);
        }
        float c = dot / (ni * norm_buf[h * TT + j] + 1e-8f);
        if (c != c) c = 0.f;                       // nan_to_num
        float p = (c + 1.f) * 0.5f;
        p_buf[row * PSTR + jj] = p;
        lsum += p;
    }

    float s = lsum;
#pragma unroll
    for (int o = 16; o > 0; o >>= 1) s += __shfl_xor_sync(0xffffffffu, s, o);
    if ((tid & 31) == 0) sred[tid >> 5] = s;
    __syncthreads();
    if (tid == 0) {
        float tot = sred[0] + sred[1] + sred[2] + sred[3];
        float gm  = (tot + 0.5f * (float)(TT - cnt)) * (1.f / (float)TT);
        denom_buf[row] = gm + 0.5f;
    }
}

// ---------------- per-head sum of 1/denom ---------------------------------
__global__ void __launch_bounds__(256)
k_suminv()
{
    const int h   = blockIdx.x;
    const int tid = threadIdx.x;   // 256
    __shared__ float sred[8];
    float s = 0.f;
    for (int t = tid; t < TT; t += 256) s += 1.f / denom_buf[h * TT + t];
#pragma unroll
    for (int o = 16; o > 0; o >>= 1) s += __shfl_xor_sync(0xffffffffu, s, o);
    if ((tid & 31) == 0) sred[tid >> 5] = s;
    __syncthreads();
    if (tid == 0) {
        float tot = 0.f;
#pragma unroll
        for (int w = 0; w < 8; ++w) tot += sred[w];
        suminv_buf[h] = tot;
    }
}

// ---------------- softmax over window + attn @ v ---------------------------
__global__ void __launch_bounds__(128)
k_attnv()
{
    const int i   = blockIdx.x;
    const int h   = blockIdx.y;
    const int tid = threadIdx.x;   // 128
    __shared__ float sattn[PSTR];
    __shared__ float sred[4];
    __shared__ float partial[128];

    const int    jstart = (i > WIN) ? (i - WIN) : 0;
    const int    cnt    = i - jstart + 1;
    const size_t row    = (size_t)(h * TT + i);
    const float  fit    = 1.f / (denom_buf[row] * suminv_buf[h]);

    const bool v0 = (tid < cnt);
    const bool v1 = (tid + 128 < cnt);
    float s0 = v0 ? fit * p_buf[row * PSTR + tid]       : -3.4e38f;
    float s1 = v1 ? fit * p_buf[row * PSTR + tid + 128] : -3.4e38f;

    // block max
    float m = fmaxf(s0, s1);
#pragma unroll
    for (int o = 16; o > 0; o >>= 1) m = fmaxf(m, __shfl_xor_sync(0xffffffffu, m, o));
    if ((tid & 31) == 0) sred[tid >> 5] = m;
    __syncthreads();
    m = fmaxf(fmaxf(sred[0], sred[1]), fmaxf(sred[2], sred[3]));
    __syncthreads();

    float e0 = v0 ? __expf(0.f) * expf(s0 - m) : 0.f;
    float e1 = v1 ? expf(s1 - m) : 0.f;
    if (v0) sattn[tid]       = e0;
    if (v1) sattn[tid + 128] = e1;

    // block sum (this sync also publishes sattn)
    float s = e0 + e1;
#pragma unroll
    for (int o = 16; o > 0; o >>= 1) s += __shfl_xor_sync(0xffffffffu, s, o);
    if ((tid & 31) == 0) sred[tid >> 5] = s;
    __syncthreads();
    s = sred[0] + sred[1] + sred[2] + sred[3];
    const float inv = 1.f / s;

    // attn @ v  (2 threads per output dim)
    const int d    = tid & 63;
    const int half = tid >> 6;
    float acc = 0.f;
    for (int jj = half; jj < cnt; jj += 2)
        acc = fmaf(sattn[jj], v_buf[(size_t)(jstart + jj) * DD + h * HDIM + d], acc);
    partial[tid] = acc;
    __syncthreads();
    if (half == 0)
        o_buf[(size_t)i * DD + h * HDIM + d] = (acc + partial[64 + tid]) * inv;
}

// ---------------- launch ---------------------------------------------------
extern "C" void kernel_launch(void* const* d_in, const int* in_sizes, int n_in,
                              void* d_out, int out_size)
{
    const float* x  = (const float*)d_in[0];
    const float* Wg = (const float*)d_in[1];
    const float* bg = (const float*)d_in[2];
    const float* Wv = (const float*)d_in[3];
    const float* bv = (const float*)d_in[4];
    const float* Wo = (const float*)d_in[5];
    const float* bo = (const float*)d_in[6];
    float* out = (float*)d_out;

    dim3 gemm_gv(DD / BN, TT / BM, 2);
    k_gv<<<gemm_gv, 256>>>(x, Wg, bg, Wv, bv);

    k_norm<<<(NH * TT) / 8, 256>>>();

    dim3 attn_grid(TT, NH);
    k_scores<<<attn_grid, 128>>>();
    k_suminv<<<NH, 256>>>();
    k_attnv<<<attn_grid, 128>>>();

    dim3 gemm_o(DD / BN, TT / BM, 1);
    k_out<<<gemm_o, 256>>>(Wo, bo, out);
}